// round 13
// baseline (speedup 1.0000x reference)
#include <cuda_runtime.h>
#include <cstdint>

// InteractingSites: per-frame all-pairs soft-core Coulomb.
// DUAL-FRAME f32x2 + LDS broadcast (R12 champion math) with 8-WARP CTAs:
// same frame-pair per CTA, work split across 8 warps so 4 CTAs/SM x 8 warps
// = 32 resident warps/SM (vs ~27 at 4-warp CTAs) for latency hiding.
//
// energy[f] = sum_{i<j} q_i q_j * rsqrt(|p_i-p_j|^2 + 1e-6)
//
// f32x2 lo half = frame A, hi half = frame B: every op / loaded byte serves
// one pair in each frame. Tiles T0..T3 (32 sites each).
// Shared table: site[tile][0][m] = (xA|xB, yA|yB), site[tile][1][m] = (zA|zB, qA|qB).
//
// Enumeration per frame (each unordered pair exactly once), split 8 ways:
//  Rectangles: m = 0..31, 6 tile combos (a<b). Warp w: m in [4w, 4w+4).
//  Triangles: per tile k: row k vs site[k][(l+dd)&31]; dd = 1..15 once each,
//    dd=16 masked to lanes 0..15. Warp w: dd in {2w+1, 2w+2} (warp 7: 15,16m).
//  -> 24 + 8 = 32 packed groups per warp, fully balanced.
//
// Charge factoring: acc_k += q_j * rsqrt (packed); row charges applied once.

#define S_SITES 128
#define CTA_THREADS 256
#define EPS2_PACKED 0x358637BD358637BDULL  // (1e-6f, 1e-6f)
#define NEG1_PACKED 0xBF800000BF800000ULL  // (-1.0f, -1.0f)
#define FULLMASK 0xFFFFFFFFu

using u64 = unsigned long long;

__device__ __forceinline__ u64 pk2(float lo, float hi) {
    u64 r;
    asm("mov.b64 %0, {%1, %2};" : "=l"(r) : "f"(lo), "f"(hi));
    return r;
}
__device__ __forceinline__ void unpk2(u64 v, float& lo, float& hi) {
    asm("mov.b64 {%0, %1}, %2;" : "=f"(lo), "=f"(hi) : "l"(v));
}
__device__ __forceinline__ u64 fma2(u64 a, u64 b, u64 c) {
    u64 d;
    asm("fma.rn.f32x2 %0, %1, %2, %3;" : "=l"(d) : "l"(a), "l"(b), "l"(c));
    return d;
}
__device__ __forceinline__ u64 rsqrt2(u64 v) {
    float lo, hi;
    unpk2(v, lo, hi);
    float rl, rh;
    asm("rsqrt.approx.f32 %0, %1;" : "=f"(rl) : "f"(lo));
    asm("rsqrt.approx.f32 %0, %1;" : "=f"(rh) : "f"(hi));
    return pk2(rl, rh);
}

// acc += jq * rsqrt(|row - j|^2 + eps), elementwise on both frame halves.
__device__ __forceinline__ void grp(u64 rx, u64 ry, u64 rz,
                                    u64 jx, u64 jy, u64 jz, u64 jq,
                                    u64& acc) {
    u64 dx = fma2(jx, (u64)NEG1_PACKED, rx);
    u64 dy = fma2(jy, (u64)NEG1_PACKED, ry);
    u64 dz = fma2(jz, (u64)NEG1_PACKED, rz);
    u64 r2 = fma2(dz, dz, (u64)EPS2_PACKED);
    r2 = fma2(dy, dy, r2);
    r2 = fma2(dx, dx, r2);
    u64 rs = rsqrt2(r2);
    acc = fma2(jq, rs, acc);
}

__global__ __launch_bounds__(CTA_THREADS, 4)
void interacting_sites_kernel(const float* __restrict__ positions,
                              const float* __restrict__ charges,
                              float* __restrict__ out,
                              int num_frames) {
    // [tile][0:(xx,yy) | 1:(zz,qq)][m] — 16B lane stride, conflict-free
    __shared__ ulonglong2 site[4][2][32];
    __shared__ float warp_sumA[8];
    __shared__ float warp_sumB[8];

    const int w = threadIdx.x >> 5;        // 0..7
    const int l = threadIdx.x & 31;

    const int fidA = blockIdx.x * 2;
    const bool hasB = (fidA + 1) < num_frames;
    const int fidB = hasB ? fidA + 1 : fidA;

    // Warps 0..3 build tile w's table entries (both frames)
    if (w < 4) {
        const long long ia = (long long)fidA * S_SITES + w * 32 + l;
        const long long ib = (long long)fidB * S_SITES + w * 32 + l;
        const float* pa = positions + ia * 3;
        const float* pb = positions + ib * 3;
        const float qa = charges[ia];
        const float qb = charges[ib];
        site[w][0][l] = make_ulonglong2(pk2(pa[0], pb[0]), pk2(pa[1], pb[1]));
        site[w][1][l] = make_ulonglong2(pk2(pa[2], pb[2]), pk2(qa, qb));
    }
    __syncthreads();

    // Rows: lane l's packed sites for all 4 tiles (from the table)
    u64 rx[4], ry[4], rz[4], rq[4];
#pragma unroll
    for (int k = 0; k < 4; ++k) {
        const ulonglong2 u = site[k][0][l];
        const ulonglong2 v = site[k][1][l];
        rx[k] = u.x;
        ry[k] = u.y;
        rz[k] = v.x;
        rq[k] = v.y;
    }

    u64 acc[4] = {0ULL, 0ULL, 0ULL, 0ULL};

    // ── Rectangles: warp w handles m in [4w, 4w+4) — broadcast LDS ──
    const int m0 = w << 2;
#pragma unroll
    for (int i = 0; i < 4; ++i) {
        const int m = m0 + i;

        const ulonglong2 u1 = site[1][0][m], v1 = site[1][1][m];
        const ulonglong2 u2 = site[2][0][m], v2 = site[2][1][m];
        const ulonglong2 u3 = site[3][0][m], v3 = site[3][1][m];

        grp(rx[0], ry[0], rz[0], u1.x, u1.y, v1.x, v1.y, acc[0]);  // T0 x T1
        grp(rx[0], ry[0], rz[0], u2.x, u2.y, v2.x, v2.y, acc[0]);  // T0 x T2
        grp(rx[0], ry[0], rz[0], u3.x, u3.y, v3.x, v3.y, acc[0]);  // T0 x T3
        grp(rx[1], ry[1], rz[1], u2.x, u2.y, v2.x, v2.y, acc[1]);  // T1 x T2
        grp(rx[1], ry[1], rz[1], u3.x, u3.y, v3.x, v3.y, acc[1]);  // T1 x T3
        grp(rx[2], ry[2], rz[2], u3.x, u3.y, v3.x, v3.y, acc[2]);  // T2 x T3
    }

    // ── Triangles: warp w handles dd in {2w+1, 2w+2}; dd=16 masked l<16 ──
#pragma unroll
    for (int i = 0; i < 2; ++i) {
        const int dd = (w << 1) + 1 + i;   // 1..16 across 8 warps
        if (dd < 16) {
            const int m = (l + dd) & 31;
#pragma unroll
            for (int k = 0; k < 4; ++k) {
                const ulonglong2 u = site[k][0][m];
                const ulonglong2 v = site[k][1][m];
                grp(rx[k], ry[k], rz[k], u.x, u.y, v.x, v.y, acc[k]);
            }
        } else if (l < 16) {               // dd = 16: each opposite pair once
            const int m = l + 16;
#pragma unroll
            for (int k = 0; k < 4; ++k) {
                const ulonglong2 u = site[k][0][m];
                const ulonglong2 v = site[k][1][m];
                grp(rx[k], ry[k], rz[k], u.x, u.y, v.x, v.y, acc[k]);
            }
        }
    }

    // Row charges applied once (packed); split halves; reduce
    u64 e = fma2(rq[0], acc[0], 0ULL);
    e = fma2(rq[1], acc[1], e);
    e = fma2(rq[2], acc[2], e);
    e = fma2(rq[3], acc[3], e);
    float eA, eB;
    unpk2(e, eA, eB);
#pragma unroll
    for (int o = 16; o > 0; o >>= 1) {
        eA += __shfl_xor_sync(FULLMASK, eA, o);
        eB += __shfl_xor_sync(FULLMASK, eB, o);
    }
    if (l == 0) {
        warp_sumA[w] = eA;
        warp_sumB[w] = eB;
    }
    __syncthreads();
    if (threadIdx.x == 0) {
        float sA = 0.f, sB = 0.f;
#pragma unroll
        for (int k = 0; k < 8; ++k) {
            sA += warp_sumA[k];
            sB += warp_sumB[k];
        }
        out[fidA] = sA;
        if (hasB) out[fidB] = sB;
    }
}

extern "C" void kernel_launch(void* const* d_in, const int* in_sizes, int n_in,
                              void* d_out, int out_size) {
    const float* positions = (const float*)d_in[0];  // [N,3] f32
    const float* charges   = (const float*)d_in[1];  // [N]   f32
    float* out = (float*)d_out;                      // [B]   f32

    const int num_frames = out_size;
    const int grid = (num_frames + 1) / 2;
    interacting_sites_kernel<<<grid, CTA_THREADS>>>(positions, charges, out, num_frames);
}

// round 14
// speedup vs baseline: 1.0074x; 1.0074x over previous
#include <cuda_runtime.h>
#include <cstdint>

// InteractingSites: per-frame all-pairs soft-core Coulomb.
// DUAL-FRAME f32x2 + LDS broadcast; 8-warp CTA covering TWO frame-pairs:
// warps 0-3 -> frames (A,B) via table 0, warps 4-7 -> frames (C,D) via table 1.
// Grid 512 -> 3.46 CTAs/SM at cap 4 -> single balanced wave.
//
// energy[f] = sum_{i<j} q_i q_j * rsqrt(|p_i-p_j|^2 + 1e-6)
//
// f32x2 lo half = first frame, hi half = second frame of the pair: every op /
// loaded byte serves one pair in each frame. Tiles T0..T3 (32 sites each).
// Shared: site[pair][tile][0][m] = (xx, yy), site[pair][tile][1][m] = (zz, qq).
//
// Enumeration per frame (each unordered pair exactly once), split across the
// 4 warps of a group (g = w & 3):
//  Rectangles: m = 0..31, 6 tile combos (a<b). Warp g: m in [8g, 8g+8).
//  Triangles: per tile k: row k vs site[k][(l+dd)&31]; dd = 1..15 once each,
//    dd=16 masked to lanes 0..15. Warps g=0..2: dd in [4g+1, 4g+5);
//    g=3: dd 13..15 + masked dd=16.
//
// Charge factoring: acc_k += q_j * rsqrt (packed); row charges applied once.

#define S_SITES 128
#define CTA_THREADS 256
#define EPS2_PACKED 0x358637BD358637BDULL  // (1e-6f, 1e-6f)
#define NEG1_PACKED 0xBF800000BF800000ULL  // (-1.0f, -1.0f)
#define FULLMASK 0xFFFFFFFFu

using u64 = unsigned long long;

__device__ __forceinline__ u64 pk2(float lo, float hi) {
    u64 r;
    asm("mov.b64 %0, {%1, %2};" : "=l"(r) : "f"(lo), "f"(hi));
    return r;
}
__device__ __forceinline__ void unpk2(u64 v, float& lo, float& hi) {
    asm("mov.b64 {%0, %1}, %2;" : "=f"(lo), "=f"(hi) : "l"(v));
}
__device__ __forceinline__ u64 fma2(u64 a, u64 b, u64 c) {
    u64 d;
    asm("fma.rn.f32x2 %0, %1, %2, %3;" : "=l"(d) : "l"(a), "l"(b), "l"(c));
    return d;
}
__device__ __forceinline__ u64 rsqrt2(u64 v) {
    float lo, hi;
    unpk2(v, lo, hi);
    float rl, rh;
    asm("rsqrt.approx.f32 %0, %1;" : "=f"(rl) : "f"(lo));
    asm("rsqrt.approx.f32 %0, %1;" : "=f"(rh) : "f"(hi));
    return pk2(rl, rh);
}

// acc += jq * rsqrt(|row - j|^2 + eps), elementwise on both frame halves.
__device__ __forceinline__ void grp(u64 rx, u64 ry, u64 rz,
                                    u64 jx, u64 jy, u64 jz, u64 jq,
                                    u64& acc) {
    u64 dx = fma2(jx, (u64)NEG1_PACKED, rx);
    u64 dy = fma2(jy, (u64)NEG1_PACKED, ry);
    u64 dz = fma2(jz, (u64)NEG1_PACKED, rz);
    u64 r2 = fma2(dz, dz, (u64)EPS2_PACKED);
    r2 = fma2(dy, dy, r2);
    r2 = fma2(dx, dx, r2);
    u64 rs = rsqrt2(r2);
    acc = fma2(jq, rs, acc);
}

__global__ __launch_bounds__(CTA_THREADS, 4)
void interacting_sites_kernel(const float* __restrict__ positions,
                              const float* __restrict__ charges,
                              float* __restrict__ out,
                              int num_frames) {
    // [pair][tile][0:(xx,yy) | 1:(zz,qq)][m] — 16B lane stride, conflict-free
    __shared__ ulonglong2 site[2][4][2][32];
    __shared__ float warp_sumA[8];
    __shared__ float warp_sumB[8];

    const int w = threadIdx.x >> 5;        // 0..7
    const int l = threadIdx.x & 31;
    const int pp = w >> 2;                 // frame-pair index within CTA (0/1)
    const int g = w & 3;                   // warp index within its 4-warp group

    // This CTA covers frames [4*bid, 4*bid+4); group pp covers (A,B) = frames
    // 4*bid + 2*pp + {0,1}.
    const int fidA = blockIdx.x * 4 + pp * 2;
    const bool hasB = (fidA + 1) < num_frames;
    const int fidB = hasB ? fidA + 1 : fidA;
    const bool hasA = fidA < num_frames;

    // Warp g of group pp builds tile g's table entries for its pair
    if (hasA) {
        const long long ia = (long long)fidA * S_SITES + g * 32 + l;
        const long long ib = (long long)fidB * S_SITES + g * 32 + l;
        const float* pa = positions + ia * 3;
        const float* pb = positions + ib * 3;
        const float qa = charges[ia];
        const float qb = charges[ib];
        site[pp][g][0][l] = make_ulonglong2(pk2(pa[0], pb[0]), pk2(pa[1], pb[1]));
        site[pp][g][1][l] = make_ulonglong2(pk2(pa[2], pb[2]), pk2(qa, qb));
    }
    __syncthreads();
    if (!hasA) return;   // only possible for trailing group when num_frames odd-ish

    // Rows: lane l's packed sites for all 4 tiles (from this pair's table)
    u64 rx[4], ry[4], rz[4], rq[4];
#pragma unroll
    for (int k = 0; k < 4; ++k) {
        const ulonglong2 u = site[pp][k][0][l];
        const ulonglong2 v = site[pp][k][1][l];
        rx[k] = u.x;
        ry[k] = u.y;
        rz[k] = v.x;
        rq[k] = v.y;
    }

    u64 acc[4] = {0ULL, 0ULL, 0ULL, 0ULL};

    // ── Rectangles: warp g handles m in [8g, 8g+8) — broadcast LDS ──
    const int m0 = g << 3;
#pragma unroll
    for (int i = 0; i < 8; ++i) {
        const int m = m0 + i;

        const ulonglong2 u1 = site[pp][1][0][m], v1 = site[pp][1][1][m];
        const ulonglong2 u2 = site[pp][2][0][m], v2 = site[pp][2][1][m];
        const ulonglong2 u3 = site[pp][3][0][m], v3 = site[pp][3][1][m];

        grp(rx[0], ry[0], rz[0], u1.x, u1.y, v1.x, v1.y, acc[0]);  // T0 x T1
        grp(rx[0], ry[0], rz[0], u2.x, u2.y, v2.x, v2.y, acc[0]);  // T0 x T2
        grp(rx[0], ry[0], rz[0], u3.x, u3.y, v3.x, v3.y, acc[0]);  // T0 x T3
        grp(rx[1], ry[1], rz[1], u2.x, u2.y, v2.x, v2.y, acc[1]);  // T1 x T2
        grp(rx[1], ry[1], rz[1], u3.x, u3.y, v3.x, v3.y, acc[1]);  // T1 x T3
        grp(rx[2], ry[2], rz[2], u3.x, u3.y, v3.x, v3.y, acc[2]);  // T2 x T3
    }

    // ── Triangles: warps g=0..2 take dd in [4g+1,4g+5); g=3: 13..15 + dd=16 ──
    const int dd0 = 1 + (g << 2);
#pragma unroll
    for (int i = 0; i < 4; ++i) {
        const int dd = dd0 + i;
        if (dd < 16) {
            const int m = (l + dd) & 31;
#pragma unroll
            for (int k = 0; k < 4; ++k) {
                const ulonglong2 u = site[pp][k][0][m];
                const ulonglong2 v = site[pp][k][1][m];
                grp(rx[k], ry[k], rz[k], u.x, u.y, v.x, v.y, acc[k]);
            }
        }
    }
    if (g == 3 && l < 16) {   // dd = 16: each opposite pair once
        const int m = l + 16;
#pragma unroll
        for (int k = 0; k < 4; ++k) {
            const ulonglong2 u = site[pp][k][0][m];
            const ulonglong2 v = site[pp][k][1][m];
            grp(rx[k], ry[k], rz[k], u.x, u.y, v.x, v.y, acc[k]);
        }
    }

    // Row charges applied once (packed); split halves; reduce within group
    u64 e = fma2(rq[0], acc[0], 0ULL);
    e = fma2(rq[1], acc[1], e);
    e = fma2(rq[2], acc[2], e);
    e = fma2(rq[3], acc[3], e);
    float eA, eB;
    unpk2(e, eA, eB);
#pragma unroll
    for (int o = 16; o > 0; o >>= 1) {
        eA += __shfl_xor_sync(FULLMASK, eA, o);
        eB += __shfl_xor_sync(FULLMASK, eB, o);
    }
    if (l == 0) {
        warp_sumA[w] = eA;
        warp_sumB[w] = eB;
    }
    __syncthreads();
    // One thread per group writes its pair's outputs
    if (l == 0 && g == 0) {
        const int b = pp << 2;
        const float sA = (warp_sumA[b] + warp_sumA[b + 1]) +
                         (warp_sumA[b + 2] + warp_sumA[b + 3]);
        const float sB = (warp_sumB[b] + warp_sumB[b + 1]) +
                         (warp_sumB[b + 2] + warp_sumB[b + 3]);
        out[fidA] = sA;
        if (hasB) out[fidB] = sB;
    }
}

extern "C" void kernel_launch(void* const* d_in, const int* in_sizes, int n_in,
                              void* d_out, int out_size) {
    const float* positions = (const float*)d_in[0];  // [N,3] f32
    const float* charges   = (const float*)d_in[1];  // [N]   f32
    float* out = (float*)d_out;                      // [B]   f32

    const int num_frames = out_size;
    const int grid = (num_frames + 3) / 4;
    interacting_sites_kernel<<<grid, CTA_THREADS>>>(positions, charges, out, num_frames);
}